// round 17
// baseline (speedup 1.0000x reference)
#include <cuda_runtime.h>

#define NB   2
#define LQ   1024
#define LIN  4096
#define CC   256
#define MH   8
#define NP   4
#define SPTS (NB*LQ*MH*NP)   /* 65536 sampling points */

// ---------------- scratch (device globals; no allocation allowed) ----------
__device__ float g_value[NB*LIN*CC];   // (B, Lin, M, D) = 8 MiB
__device__ float g_loc[SPTS*3];        // sampling locations
__device__ float g_attw[SPTS];         // softmaxed attention weights
__device__ unsigned long long g_key[SPTS];  // packed (ordered d | idx), atomicMin
__device__ float g_mid[NB*LQ*CC];      // pre-output-projection features

// ---------------- packed f32x2 helpers --------------------------------------
typedef unsigned long long u64;
__device__ __forceinline__ u64 pk2(float a, float b) {
    u64 r; asm("mov.b64 %0,{%1,%2};" : "=l"(r) : "f"(a), "f"(b)); return r;
}
__device__ __forceinline__ u64 ffma2(u64 a, u64 b, u64 c) {
    u64 d; asm("fma.rn.f32x2 %0,%1,%2,%3;" : "=l"(d) : "l"(a), "l"(b), "l"(c)); return d;
}
__device__ __forceinline__ float2 up2(u64 v) {
    float2 f; asm("mov.b64 {%0,%1},%2;" : "=f"(f.x), "=f"(f.y) : "l"(v)); return f;
}

// ---------------- tiled SGEMM-NT 64x64, K=256, BK=16, 256 thr, 4x4 ----------
// proj GEMM 2048x128 with fused location/softmax epilogue + g_key init
template<int EPI>
__global__ __launch_bounds__(256)
void sgemm_nt(const float* __restrict__ A,
              const float* __restrict__ W1, const float* __restrict__ W2, int wsplit,
              const float* __restrict__ b1, const float* __restrict__ b2,
              float* __restrict__ Out, int N,
              const float* __restrict__ qpts)
{
    __shared__ float As[16][68];
    __shared__ float Bs[16][68];
    const int tid = threadIdx.x;
    const int tx = tid & 15, ty = tid >> 4;
    const int rowBase = blockIdx.y * 64;
    const int colBase = blockIdx.x * 64;
    const int lr = tid >> 2;
    const int lc = (tid & 3) * 4;

    const float* Aptr = A + (rowBase + lr) * 256 + lc;
    const int wrow = colBase + lr;
    const float* Wptr = (wrow < wsplit) ? (W1 + wrow * 256 + lc)
                                        : (W2 + (wrow - wsplit) * 256 + lc);
    float4 ra = *(const float4*)Aptr;
    float4 rw = *(const float4*)Wptr;

    u64 acc[4][2];
    #pragma unroll
    for (int i = 0; i < 4; i++) { acc[i][0] = 0ull; acc[i][1] = 0ull; }

    for (int kt = 0; kt < 256; kt += 16) {
        As[lc+0][lr] = ra.x; As[lc+1][lr] = ra.y; As[lc+2][lr] = ra.z; As[lc+3][lr] = ra.w;
        Bs[lc+0][lr] = rw.x; Bs[lc+1][lr] = rw.y; Bs[lc+2][lr] = rw.z; Bs[lc+3][lr] = rw.w;
        __syncthreads();
        if (kt < 240) {
            ra = *(const float4*)(Aptr + kt + 16);
            rw = *(const float4*)(Wptr + kt + 16);
        }
        #pragma unroll
        for (int k = 0; k < 16; k++) {
            float4 av = *(const float4*)&As[k][ty * 4];
            float4 bv = *(const float4*)&Bs[k][tx * 4];
            u64 b01 = pk2(bv.x, bv.y), b23 = pk2(bv.z, bv.w);
            u64 a0 = pk2(av.x, av.x), a1 = pk2(av.y, av.y);
            u64 a2 = pk2(av.z, av.z), a3 = pk2(av.w, av.w);
            acc[0][0] = ffma2(a0, b01, acc[0][0]); acc[0][1] = ffma2(a0, b23, acc[0][1]);
            acc[1][0] = ffma2(a1, b01, acc[1][0]); acc[1][1] = ffma2(a1, b23, acc[1][1]);
            acc[2][0] = ffma2(a2, b01, acc[2][0]); acc[2][1] = ffma2(a2, b23, acc[2][1]);
            acc[3][0] = ffma2(a3, b01, acc[3][0]); acc[3][1] = ffma2(a3, b23, acc[3][1]);
        }
        __syncthreads();
    }

    const int c0 = colBase + tx * 4;
    float bias[4];
    #pragma unroll
    for (int j = 0; j < 4; j++) {
        int c = c0 + j;
        bias[j] = (c < wsplit) ? b1[c] : b2[c - wsplit];
    }

    #pragma unroll
    for (int i = 0; i < 4; i++) {
        const int r = rowBase + ty * 4 + i;
        float2 v01 = up2(acc[i][0]);
        float2 v23 = up2(acc[i][1]);
        float v[4] = { v01.x + bias[0], v01.y + bias[1],
                       v23.x + bias[2], v23.y + bias[3] };
        if (EPI == 0) {
            *(float4*)&Out[r * N + c0] = make_float4(v[0], v[1], v[2], v[3]);
        } else {
            if (c0 < 96) {
                #pragma unroll
                for (int j = 0; j < 4; j++) {
                    int c = c0 + j;
                    g_loc[r * 96 + c] = v[j] + qpts[r * 3 + (c % 3)];
                }
            } else {
                float m0 = fmaxf(fmaxf(v[0], v[1]), fmaxf(v[2], v[3]));
                float e0 = __expf(v[0] - m0), e1 = __expf(v[1] - m0);
                float e2 = __expf(v[2] - m0), e3 = __expf(v[3] - m0);
                float inv = 1.0f / (e0 + e1 + e2 + e3);
                int base = r * 32 + (c0 - 96);
                g_attw[base + 0] = e0 * inv;
                g_attw[base + 1] = e1 * inv;
                g_attw[base + 2] = e2 * inv;
                g_attw[base + 3] = e3 * inv;
                // free init of the atomicMin key array (exactly these 32 sp/row)
                g_key[base + 0] = ~0ull;
                g_key[base + 1] = ~0ull;
                g_key[base + 2] = ~0ull;
                g_key[base + 3] = ~0ull;
            }
        }
    }
}

// ---------------- out-projection SGEMM-NT 64x64, 512 thr, 2x4 micro ---------
// Same tile/grid as the proven 64x64 kernel (no redundant B staging), but
// 16 warps/SM for latency hiding (R7 measured the 256-thr version at
// occ 12.7%, issue 26% -> latency-bound). Threads <256 load A, >=256 load B.
__global__ __launch_bounds__(512)
void sgemm_out512(const float* __restrict__ A, const float* __restrict__ W,
                  const float* __restrict__ bias, float* __restrict__ Out, int N)
{
    __shared__ float As[16][68];
    __shared__ float Bs[16][68];
    const int tid = threadIdx.x;
    const int tx = tid & 15;          // col group: cols tx*4..+3
    const int ty = tid >> 4;          // row group: rows ty*2..+1 (0..31)
    const int rowBase = blockIdx.y * 64;
    const int colBase = blockIdx.x * 64;

    const bool loadB = tid >= 256;
    const int lt = tid & 255;
    const int lr = lt >> 2;           // 0..63
    const int lc = (lt & 3) * 4;      // 0,4,8,12
    const float* Sptr = loadB ? (W + (colBase + lr) * 256 + lc)
                              : (A + (rowBase + lr) * 256 + lc);
    float4 rv = *(const float4*)Sptr;

    u64 acc[2][2] = {{0ull, 0ull}, {0ull, 0ull}};

    for (int kt = 0; kt < 256; kt += 16) {
        float (*Ts)[68] = loadB ? Bs : As;
        Ts[lc+0][lr] = rv.x; Ts[lc+1][lr] = rv.y;
        Ts[lc+2][lr] = rv.z; Ts[lc+3][lr] = rv.w;
        __syncthreads();
        if (kt < 240) rv = *(const float4*)(Sptr + kt + 16);
        #pragma unroll
        for (int k = 0; k < 16; k++) {
            float2 av = *(const float2*)&As[k][ty * 2];
            float4 bv = *(const float4*)&Bs[k][tx * 4];
            u64 b01 = pk2(bv.x, bv.y), b23 = pk2(bv.z, bv.w);
            u64 a0 = pk2(av.x, av.x), a1 = pk2(av.y, av.y);
            acc[0][0] = ffma2(a0, b01, acc[0][0]); acc[0][1] = ffma2(a0, b23, acc[0][1]);
            acc[1][0] = ffma2(a1, b01, acc[1][0]); acc[1][1] = ffma2(a1, b23, acc[1][1]);
        }
        __syncthreads();
    }

    const int c0 = colBase + tx * 4;
    float4 bia = *(const float4*)&bias[c0];
    #pragma unroll
    for (int i = 0; i < 2; i++) {
        const int r = rowBase + ty * 2 + i;
        float2 v01 = up2(acc[i][0]);
        float2 v23 = up2(acc[i][1]);
        *(float4*)&Out[r * N + c0] =
            make_float4(v01.x + bia.x, v01.y + bia.y, v23.x + bia.z, v23.y + bia.w);
    }
}

// ---------------- tiled SGEMM-NT 128x128, K=256, BK=16, 256 thr, 8x8 --------
__global__ __launch_bounds__(256)
void sgemm128(const float* __restrict__ A, const float* __restrict__ W,
              const float* __restrict__ bias, float* __restrict__ Out, int N)
{
    __shared__ float As[16][128];
    __shared__ float Bs[16][128];
    const int tid = threadIdx.x;
    const int tx = tid & 15;
    const int ty = tid >> 4;
    const int rowBase = blockIdx.y * 128;
    const int colBase = blockIdx.x * 128;

    const int lr = tid >> 1;
    const int lk = (tid & 1) * 8;
    const float* Aptr = A + (rowBase + lr) * 256 + lk;
    const float* Wptr = W + (colBase + lr) * 256 + lk;
    float4 ra0 = *(const float4*)Aptr;
    float4 ra1 = *(const float4*)(Aptr + 4);
    float4 rw0 = *(const float4*)Wptr;
    float4 rw1 = *(const float4*)(Wptr + 4);

    u64 acc[8][4];
    #pragma unroll
    for (int i = 0; i < 8; i++)
        #pragma unroll
        for (int j = 0; j < 4; j++) acc[i][j] = 0ull;

    for (int kt = 0; kt < 256; kt += 16) {
        As[lk+0][lr] = ra0.x; As[lk+1][lr] = ra0.y; As[lk+2][lr] = ra0.z; As[lk+3][lr] = ra0.w;
        As[lk+4][lr] = ra1.x; As[lk+5][lr] = ra1.y; As[lk+6][lr] = ra1.z; As[lk+7][lr] = ra1.w;
        Bs[lk+0][lr] = rw0.x; Bs[lk+1][lr] = rw0.y; Bs[lk+2][lr] = rw0.z; Bs[lk+3][lr] = rw0.w;
        Bs[lk+4][lr] = rw1.x; Bs[lk+5][lr] = rw1.y; Bs[lk+6][lr] = rw1.z; Bs[lk+7][lr] = rw1.w;
        __syncthreads();
        if (kt < 240) {
            ra0 = *(const float4*)(Aptr + kt + 16);
            ra1 = *(const float4*)(Aptr + kt + 20);
            rw0 = *(const float4*)(Wptr + kt + 16);
            rw1 = *(const float4*)(Wptr + kt + 20);
        }
        #pragma unroll
        for (int k = 0; k < 16; k++) {
            float4 a0 = *(const float4*)&As[k][ty * 8];
            float4 a1 = *(const float4*)&As[k][ty * 8 + 4];
            float4 b0 = *(const float4*)&Bs[k][tx * 8];
            float4 b1 = *(const float4*)&Bs[k][tx * 8 + 4];
            u64 bp[4] = { pk2(b0.x, b0.y), pk2(b0.z, b0.w),
                          pk2(b1.x, b1.y), pk2(b1.z, b1.w) };
            float av[8] = { a0.x, a0.y, a0.z, a0.w, a1.x, a1.y, a1.z, a1.w };
            #pragma unroll
            for (int i = 0; i < 8; i++) {
                u64 ap = pk2(av[i], av[i]);
                #pragma unroll
                for (int j = 0; j < 4; j++)
                    acc[i][j] = ffma2(ap, bp[j], acc[i][j]);
            }
        }
        __syncthreads();
    }

    const int c0 = colBase + tx * 8;
    float4 bia0 = *(const float4*)&bias[c0];
    float4 bia1 = *(const float4*)&bias[c0 + 4];
    #pragma unroll
    for (int i = 0; i < 8; i++) {
        const int r = rowBase + ty * 8 + i;
        float2 v0 = up2(acc[i][0]), v1 = up2(acc[i][1]);
        float2 v2 = up2(acc[i][2]), v3 = up2(acc[i][3]);
        *(float4*)&Out[r * N + c0] =
            make_float4(v0.x + bia0.x, v0.y + bia0.y, v1.x + bia0.z, v1.y + bia0.w);
        *(float4*)&Out[r * N + c0 + 4] =
            make_float4(v2.x + bia1.x, v2.y + bia1.y, v3.x + bia1.z, v3.y + bia1.w);
    }
}

// ---------------- brute-force 1-NN, 8-candidate min groups -------------------
// 256 blocks = 64 s-blocks x 4 candidate quarters; 4 sampling points/thread.
// R9 structure; groups widened 4 -> 8 candidates (one compare+select per 8).
// Winning slot recovered exactly via bit-identical recompute, reverse-order
// first-equal scan. Winner published via atomicMin on packed key
// (ordered_dist<<32)|global_idx -> exact argmin with lowest-index tie-break.
__global__ __launch_bounds__(256)
void knn_kernel(const float* __restrict__ ipts)
{
    __shared__ __align__(16) float xs[1024];
    __shared__ __align__(16) float ys[1024];
    __shared__ __align__(16) float zs[1024];
    __shared__ __align__(16) float wsq[1024];

    const int tid  = threadIdx.x;
    const int sblk = blockIdx.x >> 2;      // 0..63
    const int q    = blockIdx.x & 3;       // candidate quarter
    const int sbase = sblk * 1024;
    const int b = sbase >> 15;
    const int cbase = b * LIN + q * 1024;

    for (int i = tid; i < 1024; i += 256) {
        float x = ipts[(cbase + i) * 3 + 0];
        float y = ipts[(cbase + i) * 3 + 1];
        float z = ipts[(cbase + i) * 3 + 2];
        xs[i] = x; ys[i] = y; zs[i] = z;
        wsq[i] = x * x + y * y + z * z;
    }
    __syncthreads();

    int   s[4], bg[4];
    float best[4];
    u64 ax2[4], ay2[4], az2[4];
    #pragma unroll
    for (int k = 0; k < 4; k++) {
        s[k] = sbase + k * 256 + tid;
        float sx = g_loc[3 * s[k] + 0];
        float sy = g_loc[3 * s[k] + 1];
        float sz = g_loc[3 * s[k] + 2];
        float ax = -2.0f * sx, ay = -2.0f * sy, az = -2.0f * sz;
        ax2[k] = pk2(ax, ax); ay2[k] = pk2(ay, ay); az2[k] = pk2(az, az);
        best[k] = 3.4e38f; bg[k] = 0;
    }

    const u64* X  = (const u64*)xs;
    const u64* Y  = (const u64*)ys;
    const u64* Z  = (const u64*)zs;
    const u64* Wq = (const u64*)wsq;

    // group g = candidates 8g..8g+7 (four u64 pairs)
    #pragma unroll 2
    for (int g = 0; g < 128; g++) {
        u64 x0 = X[4*g], x1 = X[4*g+1], x2 = X[4*g+2], x3 = X[4*g+3];
        u64 y0 = Y[4*g], y1 = Y[4*g+1], y2 = Y[4*g+2], y3 = Y[4*g+3];
        u64 z0 = Z[4*g], z1 = Z[4*g+1], z2 = Z[4*g+2], z3 = Z[4*g+3];
        u64 w0 = Wq[4*g], w1 = Wq[4*g+1], w2 = Wq[4*g+2], w3 = Wq[4*g+3];
        #pragma unroll
        for (int k = 0; k < 4; k++) {
            u64 d0 = ffma2(x0, ax2[k], w0); d0 = ffma2(y0, ay2[k], d0); d0 = ffma2(z0, az2[k], d0);
            u64 d1 = ffma2(x1, ax2[k], w1); d1 = ffma2(y1, ay2[k], d1); d1 = ffma2(z1, az2[k], d1);
            u64 d2 = ffma2(x2, ax2[k], w2); d2 = ffma2(y2, ay2[k], d2); d2 = ffma2(z2, az2[k], d2);
            u64 d3 = ffma2(x3, ax2[k], w3); d3 = ffma2(y3, ay2[k], d3); d3 = ffma2(z3, az2[k], d3);
            float2 f0 = up2(d0), f1 = up2(d1), f2 = up2(d2), f3 = up2(d3);
            float m = fminf(fminf(fminf(f0.x, f0.y), fminf(f1.x, f1.y)),
                            fminf(fminf(f2.x, f2.y), fminf(f3.x, f3.y)));
            if (m < best[k]) { best[k] = m; bg[k] = g; }   // strict <: earliest group
        }
    }

    // post-pass: resolve exact slot (bit-identical recompute), publish key
    #pragma unroll
    for (int k = 0; k < 4; k++) {
        int g = bg[k];
        u64 d0 = ffma2(X[4*g],   ax2[k], Wq[4*g]);
        d0 = ffma2(Y[4*g],   ay2[k], d0); d0 = ffma2(Z[4*g],   az2[k], d0);
        u64 d1 = ffma2(X[4*g+1], ax2[k], Wq[4*g+1]);
        d1 = ffma2(Y[4*g+1], ay2[k], d1); d1 = ffma2(Z[4*g+1], az2[k], d1);
        u64 d2 = ffma2(X[4*g+2], ax2[k], Wq[4*g+2]);
        d2 = ffma2(Y[4*g+2], ay2[k], d2); d2 = ffma2(Z[4*g+2], az2[k], d2);
        u64 d3 = ffma2(X[4*g+3], ax2[k], Wq[4*g+3]);
        d3 = ffma2(Y[4*g+3], ay2[k], d3); d3 = ffma2(Z[4*g+3], az2[k], d3);
        float2 f0 = up2(d0), f1 = up2(d1), f2 = up2(d2), f3 = up2(d3);
        int idx = 8*g + 7;                      // reverse order: first-equal wins
        if (f3.x == best[k]) idx = 8*g + 6;
        if (f2.y == best[k]) idx = 8*g + 5;
        if (f2.x == best[k]) idx = 8*g + 4;
        if (f1.y == best[k]) idx = 8*g + 3;
        if (f1.x == best[k]) idx = 8*g + 2;
        if (f0.y == best[k]) idx = 8*g + 1;
        if (f0.x == best[k]) idx = 8*g + 0;
        // monotone float -> ordered-uint transform (handles negative d)
        unsigned ud = __float_as_uint(best[k]);
        ud = ((int)ud < 0) ? ~ud : (ud | 0x80000000u);
        u64 key = ((u64)ud << 32) | (unsigned)(q * 1024 + idx);
        atomicMin(&g_key[s[k]], key);   // min -> smallest d, tie -> lowest idx
    }
}

// ---------------- gather + weighted sum (combine-free via g_key) ------------
__global__ __launch_bounds__(256)
void gather_kernel()
{
    const int g    = (blockIdx.x * 256 + threadIdx.x) >> 5;  // bq*8 + m
    const int lane = threadIdx.x & 31;
    const int m  = g & 7;
    const int bq = g >> 3;
    const int b  = bq >> 10;
    const int base = bq * 32 + m * 4;
    const float4 aw = *(const float4*)&g_attw[base];
    ulonglong2 k01 = *(const ulonglong2*)&g_key[base];
    ulonglong2 k23 = *(const ulonglong2*)&g_key[base + 2];
    int l0 = (int)(unsigned)(k01.x & 0xffffffffu);
    int l1 = (int)(unsigned)(k01.y & 0xffffffffu);
    int l2 = (int)(unsigned)(k23.x & 0xffffffffu);
    int l3 = (int)(unsigned)(k23.y & 0xffffffffu);
    float acc = aw.x * g_value[(b * LIN + l0) * CC + m * 32 + lane];
    acc += aw.y * g_value[(b * LIN + l1) * CC + m * 32 + lane];
    acc += aw.z * g_value[(b * LIN + l2) * CC + m * 32 + lane];
    acc += aw.w * g_value[(b * LIN + l3) * CC + m * 32 + lane];
    g_mid[bq * CC + m * 32 + lane] = acc;
}

// ---------------------------------------------------------------------------
extern "C" void kernel_launch(void* const* d_in, const int* in_sizes, int n_in,
                              void* d_out, int out_size) {
    const float* query = (const float*)d_in[0];
    const float* qpts  = (const float*)d_in[1];
    const float* inp   = (const float*)d_in[2];
    const float* ipts  = (const float*)d_in[3];
    const float* Wv    = (const float*)d_in[4];
    const float* bv    = (const float*)d_in[5];
    const float* Ws    = (const float*)d_in[6];
    const float* bs    = (const float*)d_in[7];
    const float* Wa    = (const float*)d_in[8];
    const float* ba    = (const float*)d_in[9];
    const float* Wo    = (const float*)d_in[10];
    const float* bo    = (const float*)d_in[11];
    float* out = (float*)d_out;

    float *p_value, *p_mid;
    cudaGetSymbolAddress((void**)&p_value, g_value);
    cudaGetSymbolAddress((void**)&p_mid,   g_mid);

    static cudaStream_t s1 = nullptr;
    static cudaEvent_t evFork = nullptr, evJoin = nullptr;
    if (!s1) {
        cudaStreamCreateWithFlags(&s1, cudaStreamNonBlocking);
        cudaEventCreateWithFlags(&evFork, cudaEventDisableTiming);
        cudaEventCreateWithFlags(&evJoin, cudaEventDisableTiming);
    }

    // fork: value GEMM on side stream (independent of proj/knn)
    cudaEventRecord(evFork, 0);
    cudaStreamWaitEvent(s1, evFork, 0);
    sgemm128<<<dim3(2, 64), 256, 0, s1>>>(inp, Wv, bv, p_value, 256);
    cudaEventRecord(evJoin, s1);

    // main stream: proj (-> g_loc, g_attw, g_key init), then KNN (atomicMin)
    sgemm_nt<1><<<dim3(2, 32), 256>>>(query, Ws, Wa, 96, bs, ba,
                                      nullptr, 128, qpts);
    knn_kernel<<<256, 256>>>(ipts);

    // join: gather needs knn keys and g_value
    cudaStreamWaitEvent(0, evJoin, 0);
    gather_kernel<<<2048, 256>>>();
    // output projection: 64x64 tiles, 512 threads (16 warps/SM)
    sgemm_out512<<<dim3(4, 32), 512>>>(p_mid, Wo, bo, out, 256);
}